// round 10
// baseline (speedup 1.0000x reference)
#include <cuda_runtime.h>

#define H     1024
#define HH    (H * H)
#define P     (3 * HH)
#define P4    (P / 4)
#define HH4   (HH / 4)
#define NBINS 256
#define NIDX  400000

#define EWBLK (HH4 / 256)   // 1024 blocks
#define HBLK  400           // hist/scat blocks
#define BATCH 4             // samples per thread (400*256*4 = 409600 >= NIDX)
#define NFLAG (HH / 32)     // 32768 flag words

// ---------------- device scratch (no allocation allowed) ----------------
__device__ int      g_hist[6 * NBINS];
__device__ float    g_tab[3][NBINS];      // table[b]/255 per channel
__device__ unsigned g_cnt_hist;
__device__ unsigned g_cnt_scat;
__device__ unsigned g_binD[HH];           // packed bins of ref_masked  (b0|b1<<8|b2<<16)
__device__ unsigned g_binR[HH];           // packed bins of target_masked
__device__ unsigned g_flag[NFLAG];        // dedup bitmask for scattered pixels
__device__ float    g_pew[EWBLK];         // per-block base loss partials (slot-per-block: no zeroing)
__device__ float    g_psc[HBLK];          // per-block correction partials

__device__ __forceinline__ float dn(float x) {
    float v = (x + 1.0f) * 0.5f;
    return fminf(fmaxf(v, 0.0f), 1.0f);
}

__device__ __forceinline__ int binof(float v255) {
    return min((int)v255, NBINS - 1);
}

__device__ __forceinline__ float block_reduce(float v) {
    __shared__ float ws[8];
#pragma unroll
    for (int off = 16; off; off >>= 1) v += __shfl_down_sync(0xFFFFFFFFu, v, off);
    if ((threadIdx.x & 31) == 0) ws[threadIdx.x >> 5] = v;
    __syncthreads();
    float r = 0.0f;
    if (threadIdx.x < 32) {
        r = (threadIdx.x < 8) ? ws[threadIdx.x] : 0.0f;
#pragma unroll
        for (int off = 4; off; off >>= 1) r += __shfl_down_sync(0xFFFFFFFFu, r, off);
    }
    return r;   // valid in thread 0
}

// ---------------- kernel 1: elementwise + bin packing + base loss --------
// out planes: [0:P) target_masked/255, [P:2P) ref_masked/255,
//             [2P:3P) input_masked/255, [3P:4P) input_match base (= ref_masked/255)
__global__ void ew_k(const float4* __restrict__ inp, const float4* __restrict__ tgt,
                     const float4* __restrict__ ref, const float4* __restrict__ msrc,
                     const float4* __restrict__ mtar, float4* __restrict__ out) {
    int gtid = blockIdx.x * blockDim.x + threadIdx.x;
    if (blockIdx.x == 0) {
        for (int t = threadIdx.x; t < 6 * NBINS; t += blockDim.x) g_hist[t] = 0;
        if (threadIdx.x == 0) { g_cnt_hist = 0u; g_cnt_scat = 0u; }
    }
    if (gtid < NFLAG) g_flag[gtid] = 0u;

    int i = gtid;                      // pixel-group index [0, HH4)
    float4 ms = msrc[i];
    float4 mt = mtar[i];
    float mu[4] = { ms.x != 0.0f ? 1.0f : 0.0f, ms.y != 0.0f ? 1.0f : 0.0f,
                    ms.z != 0.0f ? 1.0f : 0.0f, ms.w != 0.0f ? 1.0f : 0.0f };
    float tu[4] = { mt.x != 0.0f ? 1.0f : 0.0f, mt.y != 0.0f ? 1.0f : 0.0f,
                    mt.z != 0.0f ? 1.0f : 0.0f, mt.w != 0.0f ? 1.0f : 0.0f };
    unsigned pd[4] = {0, 0, 0, 0};
    unsigned pr[4] = {0, 0, 0, 0};
    float lsum = 0.0f;                 // sum |im - rm| over this thread's 12 values
#pragma unroll
    for (int c = 0; c < 3; c++) {
        float4 t = tgt[c * HH4 + i];
        float4 r = ref[c * HH4 + i];
        float4 in = inp[c * HH4 + i];
        float to[4] = {dn(t.x), dn(t.y), dn(t.z), dn(t.w)};
        float ro[4] = {dn(r.x), dn(r.y), dn(r.z), dn(r.w)};
        float io[4] = {fminf(fmaxf(in.x, 0.0f), 1.0f), fminf(fmaxf(in.y, 0.0f), 1.0f),
                       fminf(fmaxf(in.z, 0.0f), 1.0f), fminf(fmaxf(in.w, 0.0f), 1.0f)};
        float4 otm, orm, oim;
        float* potm = (float*)&otm; float* porm = (float*)&orm; float* poim = (float*)&oim;
#pragma unroll
        for (int j = 0; j < 4; j++) {
            float rm = ro[j] * mu[j];
            float tm = to[j] * tu[j];
            float im = io[j] * mu[j];
            potm[j] = tm;
            porm[j] = rm;
            poim[j] = im;
            lsum += fabsf(im - rm);
            pd[j] |= (unsigned)binof(rm * 255.0f) << (8 * c);
            pr[j] |= (unsigned)binof(tm * 255.0f) << (8 * c);
        }
        out[c * HH4 + i]          = otm;
        out[P4 + c * HH4 + i]     = orm;
        out[2 * P4 + c * HH4 + i] = oim;
        out[3 * P4 + c * HH4 + i] = orm;   // scatter overwrites selected pixels
    }
    ((uint4*)g_binD)[i] = make_uint4(pd[0], pd[1], pd[2], pd[3]);
    ((uint4*)g_binR)[i] = make_uint4(pr[0], pr[1], pr[2], pr[3]);

    float bs = block_reduce(lsum);
    if (threadIdx.x == 0) g_pew[blockIdx.x] = bs;
}

// ---------------- kernel 2: histograms (batched gathers) + CDF/table -----
__global__ void hist_k(const int* __restrict__ i0, const int* __restrict__ i1,
                       const int* __restrict__ i2, const int* __restrict__ i3) {
    __shared__ int sh[6 * NBINS];
    __shared__ bool last;
    for (int t = threadIdx.x; t < 6 * NBINS; t += blockDim.x) sh[t] = 0;
    __syncthreads();

    int base = blockIdx.x * blockDim.x * BATCH + threadIdx.x;
    unsigned bd[BATCH], br[BATCH];
    bool ok[BATCH];
#pragma unroll
    for (int j = 0; j < BATCH; j++) {
        int k = base + j * blockDim.x;
        ok[j] = (k < NIDX);
        int kk = ok[j] ? k : 0;
        bd[j] = g_binD[i0[kk] * H + i1[kk]];
        br[j] = g_binR[i2[kk] * H + i3[kk]];
    }
#pragma unroll
    for (int j = 0; j < BATCH; j++) {
        if (!ok[j]) continue;
        atomicAdd(&sh[bd[j] & 255u], 1);
        atomicAdd(&sh[NBINS + ((bd[j] >> 8) & 255u)], 1);
        atomicAdd(&sh[2 * NBINS + ((bd[j] >> 16) & 255u)], 1);
        atomicAdd(&sh[3 * NBINS + (br[j] & 255u)], 1);
        atomicAdd(&sh[4 * NBINS + ((br[j] >> 8) & 255u)], 1);
        atomicAdd(&sh[5 * NBINS + ((br[j] >> 16) & 255u)], 1);
    }
    __syncthreads();
    for (int t = threadIdx.x; t < 6 * NBINS; t += blockDim.x) {
        int v = sh[t];
        if (v) atomicAdd(&g_hist[t], v);
    }
    __threadfence();
    __syncthreads();
    if (threadIdx.x == 0)
        last = (atomicAdd(&g_cnt_hist, 1u) == gridDim.x - 1);
    __syncthreads();
    if (!last) return;

    // last block: CDF + transfer table.
    // Counts are integers <= 400000 < 2^24: parallel scan is exact in f32.
    __shared__ float cdf[6][NBINS];
    int b = threadIdx.x;   // 256 threads
#pragma unroll
    for (int c = 0; c < 6; c++) cdf[c][b] = (float)g_hist[c * NBINS + b];
    __syncthreads();
    for (int off = 1; off < NBINS; off <<= 1) {
        float v[6];
#pragma unroll
        for (int c = 0; c < 6; c++) v[c] = (b >= off) ? cdf[c][b - off] : 0.0f;
        __syncthreads();
#pragma unroll
        for (int c = 0; c < 6; c++) cdf[c][b] += v[c];
        __syncthreads();
    }
#pragma unroll
    for (int c = 0; c < 6; c++) cdf[c][b] = __fdiv_rn(cdf[c][b], (float)NIDX);
    __syncthreads();
#pragma unroll
    for (int c = 0; c < 3; c++) {
        int tab;
        if (b == NBINS - 1) {
            tab = NBINS - 1;
        } else {
            tab = b;
            float r = cdf[c][b];
            const float* cr = cdf[3 + c];
            for (int j = 0; j < NBINS - 1; j++) {
                if (r >= cr[j] && r <= cr[j + 1]) { tab = j + 1; break; }
            }
        }
        g_tab[c][b] = __fdiv_rn((float)tab, 255.0f);
    }
}

// ---------------- kernel 3: scatter + loss corrections + finalize ---------
__global__ void scat_k(const int* __restrict__ i0, const int* __restrict__ i1,
                       const float* __restrict__ rm_plane,   // out + P
                       const float* __restrict__ im_plane,   // out + 2P
                       float* __restrict__ o_match,          // out + 3P
                       float* __restrict__ o_loss) {         // out + 4P
    __shared__ float stab[3][NBINS];
    __shared__ bool last;
    {
        int t = threadIdx.x;
        stab[0][t] = g_tab[0][t];
        stab[1][t] = g_tab[1][t];
        stab[2][t] = g_tab[2][t];
    }
    __syncthreads();

    int base = blockIdx.x * blockDim.x * BATCH + threadIdx.x;
    int pd[BATCH];
    unsigned bd[BATCH];
    bool ok[BATCH];
#pragma unroll
    for (int j = 0; j < BATCH; j++) {
        int k = base + j * blockDim.x;
        ok[j] = (k < NIDX);
        int kk = ok[j] ? k : 0;
        pd[j] = i0[kk] * H + i1[kk];
    }
#pragma unroll
    for (int j = 0; j < BATCH; j++) bd[j] = g_binD[pd[j]];

    // gather im/rm unconditionally (max MLP; padding lanes read pixel of sample 0)
    float imv[BATCH][3], rmv[BATCH][3];
#pragma unroll
    for (int j = 0; j < BATCH; j++) {
#pragma unroll
        for (int c = 0; c < 3; c++) {
            imv[j][c] = im_plane[c * HH + pd[j]];
            rmv[j][c] = rm_plane[c * HH + pd[j]];
        }
    }

    // dedup: first toucher of each pixel applies the loss correction
    bool first[BATCH];
#pragma unroll
    for (int j = 0; j < BATCH; j++) {
        first[j] = false;
        if (ok[j]) {
            unsigned m = 1u << (pd[j] & 31);
            unsigned old = atomicOr(&g_flag[pd[j] >> 5], m);
            first[j] = ((old & m) == 0u);
        }
    }

    float corr = 0.0f;
#pragma unroll
    for (int j = 0; j < BATCH; j++) {
        float t0 = stab[0][bd[j] & 255u];
        float t1 = stab[1][(bd[j] >> 8) & 255u];
        float t2 = stab[2][(bd[j] >> 16) & 255u];
        if (first[j]) {
            corr += (fabsf(imv[j][0] - t0) - fabsf(imv[j][0] - rmv[j][0]))
                  + (fabsf(imv[j][1] - t1) - fabsf(imv[j][1] - rmv[j][1]))
                  + (fabsf(imv[j][2] - t2) - fabsf(imv[j][2] - rmv[j][2]));
        }
        if (ok[j]) {
            o_match[pd[j]]          = t0;   // duplicates write identical values
            o_match[HH + pd[j]]     = t1;
            o_match[2 * HH + pd[j]] = t2;
        }
    }

    float bs = block_reduce(corr);
    if (threadIdx.x == 0) {
        g_psc[blockIdx.x] = bs;
        __threadfence();
        last = (atomicAdd(&g_cnt_scat, 1u) == gridDim.x - 1);
    }
    __syncthreads();
    if (!last) return;

    // final block: total = sum(g_pew) + sum(g_psc), write loss
    __shared__ double sred[256];
    double tot = 0.0;
    for (int i = threadIdx.x; i < EWBLK; i += blockDim.x) tot += (double)g_pew[i];
    for (int i = threadIdx.x; i < HBLK; i += blockDim.x) tot += (double)g_psc[i];
    sred[threadIdx.x] = tot;
    __syncthreads();
    for (int s = 128; s; s >>= 1) {
        if (threadIdx.x < s) sred[threadIdx.x] += sred[threadIdx.x + s];
        __syncthreads();
    }
    if (threadIdx.x == 0) o_loss[0] = (float)(sred[0] / (double)P);
}

// ---------------- launch -------------------------------------------------
extern "C" void kernel_launch(void* const* d_in, const int* in_sizes, int n_in,
                              void* d_out, int out_size) {
    const float* inp  = (const float*)d_in[0];
    const float* tgt  = (const float*)d_in[1];
    const float* ref  = (const float*)d_in[2];
    const float* msrc = (const float*)d_in[3];
    const float* mtar = (const float*)d_in[4];
    // d_in[5] = target_data_eye (unused by reference)
    const int* i0 = (const int*)d_in[6];
    const int* i1 = (const int*)d_in[7];
    const int* i2 = (const int*)d_in[8];
    const int* i3 = (const int*)d_in[9];
    float* out = (float*)d_out;

    ew_k<<<EWBLK, 256>>>((const float4*)inp, (const float4*)tgt,
                         (const float4*)ref, (const float4*)msrc,
                         (const float4*)mtar, (float4*)out);
    hist_k<<<HBLK, 256>>>(i0, i1, i2, i3);
    scat_k<<<HBLK, 256>>>(i0, i1,
                          out + (size_t)P,       // ref_masked plane
                          out + (size_t)2 * P,   // input_masked plane
                          out + (size_t)3 * P,   // match plane
                          out + (size_t)4 * P);  // loss scalar
}

// round 11
// speedup vs baseline: 1.1188x; 1.1188x over previous
#include <cuda_runtime.h>

#define H     1024
#define HH    (H * H)
#define P     (3 * HH)
#define P4    (P / 4)
#define HH4   (HH / 4)
#define NBINS 256
#define NIDX  400000

#define EWBLK (HH4 / 256)   // 1024 blocks
#define HBLK  400           // hist/scat blocks
#define BATCH 4             // samples per thread (400*256*4 = 409600 >= NIDX)
#define LBLK  1024          // loss blocks: 1024*256*3 = 786432 = P4
#define LBATCH 3

// ---------------- device scratch (no allocation allowed) ----------------
__device__ int      g_hist[6 * NBINS];
__device__ float    g_tab[3][NBINS];      // table[b]/255 per channel
__device__ unsigned g_cnt_hist;
__device__ unsigned g_cnt_loss;
__device__ unsigned g_binD[HH];           // packed bins of ref_masked  (b0|b1<<8|b2<<16)
__device__ unsigned g_binR[HH];           // packed bins of target_masked
__device__ float    g_pls[LBLK];          // per-block loss partials (slot-per-block: no zeroing)

__device__ __forceinline__ float dn(float x) {
    float v = (x + 1.0f) * 0.5f;
    return fminf(fmaxf(v, 0.0f), 1.0f);
}

__device__ __forceinline__ int binof(float v255) {
    return min((int)v255, NBINS - 1);
}

__device__ __forceinline__ float block_reduce(float v) {
    __shared__ float ws[8];
#pragma unroll
    for (int off = 16; off; off >>= 1) v += __shfl_down_sync(0xFFFFFFFFu, v, off);
    if ((threadIdx.x & 31) == 0) ws[threadIdx.x >> 5] = v;
    __syncthreads();
    float r = 0.0f;
    if (threadIdx.x < 32) {
        r = (threadIdx.x < 8) ? ws[threadIdx.x] : 0.0f;
#pragma unroll
        for (int off = 4; off; off >>= 1) r += __shfl_down_sync(0xFFFFFFFFu, r, off);
    }
    return r;   // valid in thread 0
}

// ---------------- kernel 1: elementwise transforms + bin packing ---------
// out planes: [0:P) target_masked/255, [P:2P) ref_masked/255,
//             [2P:3P) input_masked/255, [3P:4P) input_match base (= ref_masked/255)
__global__ void ew_k(const float4* __restrict__ inp, const float4* __restrict__ tgt,
                     const float4* __restrict__ ref, const float4* __restrict__ msrc,
                     const float4* __restrict__ mtar, float4* __restrict__ out) {
    if (blockIdx.x == 0) {
        for (int t = threadIdx.x; t < 6 * NBINS; t += blockDim.x) g_hist[t] = 0;
        if (threadIdx.x == 0) { g_cnt_hist = 0u; g_cnt_loss = 0u; }
    }
    int i = blockIdx.x * blockDim.x + threadIdx.x;   // pixel-group index [0, HH4)
    float4 ms = msrc[i];
    float4 mt = mtar[i];
    float mu[4] = { ms.x != 0.0f ? 1.0f : 0.0f, ms.y != 0.0f ? 1.0f : 0.0f,
                    ms.z != 0.0f ? 1.0f : 0.0f, ms.w != 0.0f ? 1.0f : 0.0f };
    float tu[4] = { mt.x != 0.0f ? 1.0f : 0.0f, mt.y != 0.0f ? 1.0f : 0.0f,
                    mt.z != 0.0f ? 1.0f : 0.0f, mt.w != 0.0f ? 1.0f : 0.0f };
    unsigned pd[4] = {0, 0, 0, 0};
    unsigned pr[4] = {0, 0, 0, 0};
#pragma unroll
    for (int c = 0; c < 3; c++) {
        float4 t = tgt[c * HH4 + i];
        float4 r = ref[c * HH4 + i];
        float4 in = inp[c * HH4 + i];
        float to[4] = {dn(t.x), dn(t.y), dn(t.z), dn(t.w)};
        float ro[4] = {dn(r.x), dn(r.y), dn(r.z), dn(r.w)};
        float io[4] = {fminf(fmaxf(in.x, 0.0f), 1.0f), fminf(fmaxf(in.y, 0.0f), 1.0f),
                       fminf(fmaxf(in.z, 0.0f), 1.0f), fminf(fmaxf(in.w, 0.0f), 1.0f)};
        float4 otm, orm, oim;
        float* potm = (float*)&otm; float* porm = (float*)&orm; float* poim = (float*)&oim;
#pragma unroll
        for (int j = 0; j < 4; j++) {
            float rm = ro[j] * mu[j];
            float tm = to[j] * tu[j];
            potm[j] = tm;
            porm[j] = rm;
            poim[j] = io[j] * mu[j];
            pd[j] |= (unsigned)binof(rm * 255.0f) << (8 * c);
            pr[j] |= (unsigned)binof(tm * 255.0f) << (8 * c);
        }
        out[c * HH4 + i]          = otm;
        out[P4 + c * HH4 + i]     = orm;
        out[2 * P4 + c * HH4 + i] = oim;
        out[3 * P4 + c * HH4 + i] = orm;   // scatter overwrites selected pixels
    }
    ((uint4*)g_binD)[i] = make_uint4(pd[0], pd[1], pd[2], pd[3]);
    ((uint4*)g_binR)[i] = make_uint4(pr[0], pr[1], pr[2], pr[3]);
}

// ---------------- kernel 2: histograms (batched gathers) + CDF/table -----
__global__ void hist_k(const int* __restrict__ i0, const int* __restrict__ i1,
                       const int* __restrict__ i2, const int* __restrict__ i3) {
    __shared__ int sh[6 * NBINS];
    __shared__ bool last;
    for (int t = threadIdx.x; t < 6 * NBINS; t += blockDim.x) sh[t] = 0;
    __syncthreads();

    int base = blockIdx.x * blockDim.x * BATCH + threadIdx.x;
    unsigned bd[BATCH], br[BATCH];
    bool ok[BATCH];
#pragma unroll
    for (int j = 0; j < BATCH; j++) {
        int k = base + j * blockDim.x;
        ok[j] = (k < NIDX);
        int kk = ok[j] ? k : 0;
        bd[j] = g_binD[i0[kk] * H + i1[kk]];
        br[j] = g_binR[i2[kk] * H + i3[kk]];
    }
#pragma unroll
    for (int j = 0; j < BATCH; j++) {
        if (!ok[j]) continue;
        atomicAdd(&sh[bd[j] & 255u], 1);
        atomicAdd(&sh[NBINS + ((bd[j] >> 8) & 255u)], 1);
        atomicAdd(&sh[2 * NBINS + ((bd[j] >> 16) & 255u)], 1);
        atomicAdd(&sh[3 * NBINS + (br[j] & 255u)], 1);
        atomicAdd(&sh[4 * NBINS + ((br[j] >> 8) & 255u)], 1);
        atomicAdd(&sh[5 * NBINS + ((br[j] >> 16) & 255u)], 1);
    }
    __syncthreads();
    for (int t = threadIdx.x; t < 6 * NBINS; t += blockDim.x) {
        int v = sh[t];
        if (v) atomicAdd(&g_hist[t], v);
    }
    __threadfence();
    __syncthreads();
    if (threadIdx.x == 0)
        last = (atomicAdd(&g_cnt_hist, 1u) == gridDim.x - 1);
    __syncthreads();
    if (!last) return;

    // last block: CDF + transfer table.
    // Counts are integers <= 400000 < 2^24: parallel scan is exact in f32.
    __shared__ float cdf[6][NBINS];
    int b = threadIdx.x;   // 256 threads
#pragma unroll
    for (int c = 0; c < 6; c++) cdf[c][b] = (float)g_hist[c * NBINS + b];
    __syncthreads();
    for (int off = 1; off < NBINS; off <<= 1) {
        float v[6];
#pragma unroll
        for (int c = 0; c < 6; c++) v[c] = (b >= off) ? cdf[c][b - off] : 0.0f;
        __syncthreads();
#pragma unroll
        for (int c = 0; c < 6; c++) cdf[c][b] += v[c];
        __syncthreads();
    }
#pragma unroll
    for (int c = 0; c < 6; c++) cdf[c][b] = __fdiv_rn(cdf[c][b], (float)NIDX);
    __syncthreads();
#pragma unroll
    for (int c = 0; c < 3; c++) {
        int tab;
        if (b == NBINS - 1) {
            tab = NBINS - 1;
        } else {
            tab = b;
            float r = cdf[c][b];
            const float* cr = cdf[3 + c];
            for (int j = 0; j < NBINS - 1; j++) {
                if (r >= cr[j] && r <= cr[j + 1]) { tab = j + 1; break; }
            }
        }
        g_tab[c][b] = __fdiv_rn((float)tab, 255.0f);
    }
}

// ---------------- kernel 3: scatter matched values (batched, minimal) -----
__global__ void scat_k(const int* __restrict__ i0, const int* __restrict__ i1,
                       float* __restrict__ o_match) {
    __shared__ float stab[3][NBINS];
    {
        int t = threadIdx.x;
        stab[0][t] = g_tab[0][t];
        stab[1][t] = g_tab[1][t];
        stab[2][t] = g_tab[2][t];
    }
    __syncthreads();
    int base = blockIdx.x * blockDim.x * BATCH + threadIdx.x;
    int pd[BATCH];
    unsigned bd[BATCH];
    bool ok[BATCH];
#pragma unroll
    for (int j = 0; j < BATCH; j++) {
        int k = base + j * blockDim.x;
        ok[j] = (k < NIDX);
        int kk = ok[j] ? k : 0;
        pd[j] = i0[kk] * H + i1[kk];
    }
#pragma unroll
    for (int j = 0; j < BATCH; j++) bd[j] = g_binD[pd[j]];
#pragma unroll
    for (int j = 0; j < BATCH; j++) {
        if (!ok[j]) continue;
        o_match[pd[j]]          = stab[0][bd[j] & 255u];   // duplicates write identical values
        o_match[HH + pd[j]]     = stab[1][(bd[j] >> 8) & 255u];
        o_match[2 * HH + pd[j]] = stab[2][(bd[j] >> 16) & 255u];
    }
}

// ---------------- kernel 4: L1 mean reduction (batched) + finalize --------
__global__ void loss_k(const float4* __restrict__ a, const float4* __restrict__ b,
                       float* __restrict__ o_loss) {
    __shared__ bool last;
    // block covers LBATCH*256 consecutive float4s; all loads front-issued (MLP=6)
    int base = blockIdx.x * blockDim.x * LBATCH + threadIdx.x;
    float4 x[LBATCH], y[LBATCH];
#pragma unroll
    for (int j = 0; j < LBATCH; j++) {
        x[j] = a[base + j * blockDim.x];
        y[j] = b[base + j * blockDim.x];
    }
    float local = 0.0f;
#pragma unroll
    for (int j = 0; j < LBATCH; j++) {
        local += fabsf(x[j].x - y[j].x) + fabsf(x[j].y - y[j].y) +
                 fabsf(x[j].z - y[j].z) + fabsf(x[j].w - y[j].w);
    }
    float bs = block_reduce(local);
    if (threadIdx.x == 0) {
        g_pls[blockIdx.x] = bs;
        __threadfence();
        last = (atomicAdd(&g_cnt_loss, 1u) == gridDim.x - 1);
    }
    __syncthreads();
    if (!last) return;

    __shared__ double sred[256];
    double tot = 0.0;
    for (int i = threadIdx.x; i < LBLK; i += blockDim.x) tot += (double)g_pls[i];
    sred[threadIdx.x] = tot;
    __syncthreads();
    for (int s = 128; s; s >>= 1) {
        if (threadIdx.x < s) sred[threadIdx.x] += sred[threadIdx.x + s];
        __syncthreads();
    }
    if (threadIdx.x == 0) o_loss[0] = (float)(sred[0] / (double)P);
}

// ---------------- launch -------------------------------------------------
extern "C" void kernel_launch(void* const* d_in, const int* in_sizes, int n_in,
                              void* d_out, int out_size) {
    const float* inp  = (const float*)d_in[0];
    const float* tgt  = (const float*)d_in[1];
    const float* ref  = (const float*)d_in[2];
    const float* msrc = (const float*)d_in[3];
    const float* mtar = (const float*)d_in[4];
    // d_in[5] = target_data_eye (unused by reference)
    const int* i0 = (const int*)d_in[6];
    const int* i1 = (const int*)d_in[7];
    const int* i2 = (const int*)d_in[8];
    const int* i3 = (const int*)d_in[9];
    float* out = (float*)d_out;

    ew_k<<<EWBLK, 256>>>((const float4*)inp, (const float4*)tgt,
                         (const float4*)ref, (const float4*)msrc,
                         (const float4*)mtar, (float4*)out);
    hist_k<<<HBLK, 256>>>(i0, i1, i2, i3);
    scat_k<<<HBLK, 256>>>(i0, i1, out + (size_t)3 * P);
    loss_k<<<LBLK, 256>>>((const float4*)(out + (size_t)2 * P),
                          (const float4*)(out + (size_t)3 * P),
                          out + (size_t)4 * P);
}

// round 13
// speedup vs baseline: 1.2120x; 1.0833x over previous
#include <cuda_runtime.h>

#define H      1024
#define HH     (H * H)
#define P      (3 * HH)
#define P4     (P / 4)
#define HH4    (HH / 4)
#define NBINS  256
#define NIDX   400000

#define GRID   512
#define TPB    256
#define EW_IT  (HH4 / (GRID * TPB))   // 2
#define HBATCH 4                      // 512*256*4 = 524288 >= NIDX
#define LBATCH (P4 / (GRID * TPB))    // 6 (exact)

// ---------------- device scratch (no allocation allowed) ----------------
__device__ int                g_hist[6 * NBINS];
__device__ unsigned           g_binD[HH];   // packed bins of ref_masked  (b0|b1<<8|b2<<16)
__device__ unsigned           g_binR[HH];   // packed bins of target_masked
__device__ float              g_pls[GRID];  // per-block loss partials (slot-per-block)
__device__ unsigned long long g_tick;       // monotonic barrier ticket (never reset)

__device__ __forceinline__ float dn(float x) {
    float v = (x + 1.0f) * 0.5f;
    return fminf(fmaxf(v, 0.0f), 1.0f);
}
__device__ __forceinline__ int binof(float v255) { return min((int)v255, NBINS - 1); }

// Device-wide barrier. Monotonic ticket: all blocks hit every barrier, so
// arrivals group into consecutive runs of GRID; target = next multiple of GRID.
// Safe across graph replays with no reset. spin=false -> arrive-only (exit path).
__device__ __forceinline__ void gsync(bool spin) {
    __syncthreads();
    if (threadIdx.x == 0) {
        __threadfence();                                   // release prior writes
        unsigned long long t = atomicAdd(&g_tick, 1ULL) + 1ULL;
        if (spin) {
            unsigned long long tgt = ((t + GRID - 1) / GRID) * (unsigned long long)GRID;
            unsigned long long cur;
            do {
                asm volatile("ld.global.acquire.gpu.u64 %0, [%1];"
                             : "=l"(cur) : "l"(&g_tick));
                if (cur >= tgt) break;
                __nanosleep(64);
            } while (true);
        }
    }
    __syncthreads();
}

__global__ void __launch_bounds__(TPB, 4)
mega_k(const float4* __restrict__ inp, const float4* __restrict__ tgt,
       const float4* __restrict__ ref, const float4* __restrict__ msrc,
       const float4* __restrict__ mtar,
       const int* __restrict__ i0, const int* __restrict__ i1,
       const int* __restrict__ i2, const int* __restrict__ i3,
       float4* __restrict__ out) {
    __shared__ int   sh[6 * NBINS];
    __shared__ float cdf[6][NBINS];
    __shared__ float stab[3][NBINS];
    const int tid = threadIdx.x;
    const int bid = blockIdx.x;
    float* outf = (float*)out;

    // ============ Phase A: elementwise transforms + bin packing ==========
    if (bid == 0)
        for (int t = tid; t < 6 * NBINS; t += TPB) g_hist[t] = 0;
    {
        int base = bid * (TPB * EW_IT);
#pragma unroll
        for (int it = 0; it < EW_IT; it++) {
            int i = base + it * TPB + tid;           // [0, HH4)
            float4 ms = msrc[i];
            float4 mt = mtar[i];
            float mu[4] = { ms.x != 0.0f ? 1.0f : 0.0f, ms.y != 0.0f ? 1.0f : 0.0f,
                            ms.z != 0.0f ? 1.0f : 0.0f, ms.w != 0.0f ? 1.0f : 0.0f };
            float tu[4] = { mt.x != 0.0f ? 1.0f : 0.0f, mt.y != 0.0f ? 1.0f : 0.0f,
                            mt.z != 0.0f ? 1.0f : 0.0f, mt.w != 0.0f ? 1.0f : 0.0f };
            unsigned pd[4] = {0, 0, 0, 0};
            unsigned pr[4] = {0, 0, 0, 0};
#pragma unroll
            for (int c = 0; c < 3; c++) {
                float4 t = tgt[c * HH4 + i];
                float4 r = ref[c * HH4 + i];
                float4 in = inp[c * HH4 + i];
                float to[4] = {dn(t.x), dn(t.y), dn(t.z), dn(t.w)};
                float ro[4] = {dn(r.x), dn(r.y), dn(r.z), dn(r.w)};
                float io[4] = {fminf(fmaxf(in.x, 0.0f), 1.0f), fminf(fmaxf(in.y, 0.0f), 1.0f),
                               fminf(fmaxf(in.z, 0.0f), 1.0f), fminf(fmaxf(in.w, 0.0f), 1.0f)};
                float4 otm, orm, oim;
                float* potm = (float*)&otm; float* porm = (float*)&orm; float* poim = (float*)&oim;
#pragma unroll
                for (int j = 0; j < 4; j++) {
                    float rm = ro[j] * mu[j];
                    float tm = to[j] * tu[j];
                    potm[j] = tm;
                    porm[j] = rm;
                    poim[j] = io[j] * mu[j];
                    pd[j] |= (unsigned)binof(rm * 255.0f) << (8 * c);
                    pr[j] |= (unsigned)binof(tm * 255.0f) << (8 * c);
                }
                out[c * HH4 + i]          = otm;
                out[P4 + c * HH4 + i]     = orm;
                out[2 * P4 + c * HH4 + i] = oim;
                out[3 * P4 + c * HH4 + i] = orm;   // scatter overwrites selected pixels
            }
            ((uint4*)g_binD)[i] = make_uint4(pd[0], pd[1], pd[2], pd[3]);
            ((uint4*)g_binR)[i] = make_uint4(pr[0], pr[1], pr[2], pr[3]);
        }
    }
    gsync(true);   // barrier 1: bins + hist-zero visible

    // ============ Phase B: privatized histograms =========================
    for (int t = tid; t < 6 * NBINS; t += TPB) sh[t] = 0;
    __syncthreads();
    {
        int base = bid * TPB * HBATCH + tid;
        unsigned bd[HBATCH], br[HBATCH];
        bool ok[HBATCH];
#pragma unroll
        for (int j = 0; j < HBATCH; j++) {
            int k = base + j * TPB;
            ok[j] = (k < NIDX);
            int kk = ok[j] ? k : 0;
            bd[j] = g_binD[i0[kk] * H + i1[kk]];
            br[j] = g_binR[i2[kk] * H + i3[kk]];
        }
#pragma unroll
        for (int j = 0; j < HBATCH; j++) {
            if (!ok[j]) continue;
            atomicAdd(&sh[bd[j] & 255u], 1);
            atomicAdd(&sh[NBINS + ((bd[j] >> 8) & 255u)], 1);
            atomicAdd(&sh[2 * NBINS + ((bd[j] >> 16) & 255u)], 1);
            atomicAdd(&sh[3 * NBINS + (br[j] & 255u)], 1);
            atomicAdd(&sh[4 * NBINS + ((br[j] >> 8) & 255u)], 1);
            atomicAdd(&sh[5 * NBINS + ((br[j] >> 16) & 255u)], 1);
        }
        __syncthreads();
        for (int t = tid; t < 6 * NBINS; t += TPB) {
            int v = sh[t];
            if (v) atomicAdd(&g_hist[t], v);
        }
    }
    gsync(true);   // barrier 2: full histogram visible

    // ============ Phase C: per-block table (redundant) + scatter =========
    {
        int b = tid;   // 256 threads
        // counts are integers <= 400000 < 2^24: parallel scan is exact in f32
#pragma unroll
        for (int c = 0; c < 6; c++) cdf[c][b] = (float)g_hist[c * NBINS + b];
        __syncthreads();
        for (int off = 1; off < NBINS; off <<= 1) {
            float v[6];
#pragma unroll
            for (int c = 0; c < 6; c++) v[c] = (b >= off) ? cdf[c][b - off] : 0.0f;
            __syncthreads();
#pragma unroll
            for (int c = 0; c < 6; c++) cdf[c][b] += v[c];
            __syncthreads();
        }
#pragma unroll
        for (int c = 0; c < 6; c++) cdf[c][b] = __fdiv_rn(cdf[c][b], (float)NIDX);
        __syncthreads();
#pragma unroll
        for (int c = 0; c < 3; c++) {
            int tab;
            if (b == NBINS - 1) {
                tab = NBINS - 1;
            } else {
                tab = b;
                float r = cdf[c][b];
                const float* cr = cdf[3 + c];
                for (int j = 0; j < NBINS - 1; j++) {
                    if (r >= cr[j] && r <= cr[j + 1]) { tab = j + 1; break; }
                }
            }
            stab[c][b] = __fdiv_rn((float)tab, 255.0f);
        }
        __syncthreads();

        // scatter matched values
        float* o_match = outf + (size_t)3 * P;
        int base = bid * TPB * HBATCH + tid;
        int pd[HBATCH];
        unsigned bd[HBATCH];
        bool ok[HBATCH];
#pragma unroll
        for (int j = 0; j < HBATCH; j++) {
            int k = base + j * TPB;
            ok[j] = (k < NIDX);
            int kk = ok[j] ? k : 0;
            pd[j] = i0[kk] * H + i1[kk];
        }
#pragma unroll
        for (int j = 0; j < HBATCH; j++) bd[j] = g_binD[pd[j]];
#pragma unroll
        for (int j = 0; j < HBATCH; j++) {
            if (!ok[j]) continue;
            o_match[pd[j]]          = stab[0][bd[j] & 255u];   // duplicates write identical values
            o_match[HH + pd[j]]     = stab[1][(bd[j] >> 8) & 255u];
            o_match[2 * HH + pd[j]] = stab[2][(bd[j] >> 16) & 255u];
        }
    }
    gsync(true);   // barrier 3: match plane complete

    // ============ Phase D: L1 mean over |im - match| =====================
    {
        const float4* a = (const float4*)(outf + (size_t)2 * P);   // input_masked
        const float4* b4 = (const float4*)(outf + (size_t)3 * P);  // input_match
        int base = bid * TPB * LBATCH + tid;
        float4 x[LBATCH], y[LBATCH];
#pragma unroll
        for (int j = 0; j < LBATCH; j++) {
            x[j] = a[base + j * TPB];
            y[j] = b4[base + j * TPB];
        }
        float local = 0.0f;
#pragma unroll
        for (int j = 0; j < LBATCH; j++) {
            local += fabsf(x[j].x - y[j].x) + fabsf(x[j].y - y[j].y) +
                     fabsf(x[j].z - y[j].z) + fabsf(x[j].w - y[j].w);
        }
        // block reduce
        __shared__ float ws[8];
#pragma unroll
        for (int off = 16; off; off >>= 1) local += __shfl_down_sync(0xFFFFFFFFu, local, off);
        if ((tid & 31) == 0) ws[tid >> 5] = local;
        __syncthreads();
        if (tid < 32) {
            float v = (tid < 8) ? ws[tid] : 0.0f;
#pragma unroll
            for (int off = 4; off; off >>= 1) v += __shfl_down_sync(0xFFFFFFFFu, v, off);
            if (tid == 0) g_pls[bid] = v;
        }
    }
    gsync(bid == 0);   // barrier 4: partials visible; only block 0 spins

    if (bid != 0) return;

    // ============ block 0: final reduction + write loss ==================
    {
        __shared__ double sred[TPB];
        double tot = 0.0;
        for (int i = tid; i < GRID; i += TPB) tot += (double)g_pls[i];
        sred[tid] = tot;
        __syncthreads();
        for (int s = TPB / 2; s; s >>= 1) {
            if (tid < s) sred[tid] += sred[tid + s];
            __syncthreads();
        }
        if (tid == 0) outf[(size_t)4 * P] = (float)(sred[0] / (double)P);
    }
}

// ---------------- launch -------------------------------------------------
extern "C" void kernel_launch(void* const* d_in, const int* in_sizes, int n_in,
                              void* d_out, int out_size) {
    const float* inp  = (const float*)d_in[0];
    const float* tgt  = (const float*)d_in[1];
    const float* ref  = (const float*)d_in[2];
    const float* msrc = (const float*)d_in[3];
    const float* mtar = (const float*)d_in[4];
    // d_in[5] = target_data_eye (unused by reference)
    const int* i0 = (const int*)d_in[6];
    const int* i1 = (const int*)d_in[7];
    const int* i2 = (const int*)d_in[8];
    const int* i3 = (const int*)d_in[9];

    mega_k<<<GRID, TPB>>>((const float4*)inp, (const float4*)tgt,
                          (const float4*)ref, (const float4*)msrc,
                          (const float4*)mtar, i0, i1, i2, i3,
                          (float4*)d_out);
}

// round 14
// speedup vs baseline: 1.9031x; 1.5702x over previous
#include <cuda_runtime.h>

#define H      1024
#define HH     (H * H)
#define P      (3 * HH)
#define P4     (P / 4)
#define HH4    (HH / 4)
#define NBINS  256
#define NIDX   400000
#define NFLAG  (HH / 32)              // 32768 bitmap words

#define GRID   512
#define TPB    256
#define EW_IT  (HH4 / (GRID * TPB))   // 2
#define HBATCH 4                      // 512*256*4 = 524288 >= NIDX

// ---------------- device scratch (no allocation allowed) ----------------
__device__ int                g_hist[6 * NBINS];
__device__ unsigned           g_binD[HH];   // packed bins of ref_masked (b0|b1<<8|b2<<16)
__device__ unsigned           g_binR[HH];   // packed bins of target_masked
__device__ unsigned           g_flag[NFLAG];// "pixel was scattered" bitmap
__device__ float              g_pls[GRID];  // per-block loss partials (slot-per-block)
__device__ unsigned long long g_tick;       // monotonic barrier ticket (never reset)

__device__ __forceinline__ float dn(float x) {
    float v = (x + 1.0f) * 0.5f;
    return fminf(fmaxf(v, 0.0f), 1.0f);
}
__device__ __forceinline__ int binof(float v255) { return min((int)v255, NBINS - 1); }

// Device-wide barrier: monotonic ticket, all blocks hit every barrier, so
// arrivals group into consecutive runs of GRID. Safe across graph replays.
__device__ __forceinline__ void gsync(bool spin) {
    __syncthreads();
    if (threadIdx.x == 0) {
        __threadfence();
        unsigned long long t = atomicAdd(&g_tick, 1ULL) + 1ULL;
        if (spin) {
            unsigned long long tgt = ((t + GRID - 1) / GRID) * (unsigned long long)GRID;
            unsigned long long cur;
            do {
                asm volatile("ld.global.acquire.gpu.u64 %0, [%1];"
                             : "=l"(cur) : "l"(&g_tick));
                if (cur >= tgt) break;
                __nanosleep(64);
            } while (true);
        }
    }
    __syncthreads();
}

__global__ void __launch_bounds__(TPB, 4)
mega_k(const float4* __restrict__ inp, const float4* __restrict__ tgt,
       const float4* __restrict__ ref, const float4* __restrict__ msrc,
       const float4* __restrict__ mtar,
       const int* __restrict__ i0, const int* __restrict__ i1,
       const int* __restrict__ i2, const int* __restrict__ i3,
       float4* __restrict__ out) {
    __shared__ int   sh[6 * NBINS];
    __shared__ float cdf[6][NBINS];
    __shared__ float stab[3][NBINS];
    const int tid = threadIdx.x;
    const int bid = blockIdx.x;
    float* outf = (float*)out;

    // ============ Phase A: elementwise transforms + bin packing ==========
    // (match plane NOT written here; built coalesced in phase C)
    if (bid == 0)
        for (int t = tid; t < 6 * NBINS; t += TPB) g_hist[t] = 0;
    {
        int gtid = bid * TPB + tid;
        if (gtid < NFLAG) g_flag[gtid] = 0u;
    }
    {
        int base = bid * (TPB * EW_IT);
#pragma unroll
        for (int it = 0; it < EW_IT; it++) {
            int i = base + it * TPB + tid;           // pixel-group [0, HH4)
            float4 ms = msrc[i];
            float4 mt = mtar[i];
            float mu[4] = { ms.x != 0.0f ? 1.0f : 0.0f, ms.y != 0.0f ? 1.0f : 0.0f,
                            ms.z != 0.0f ? 1.0f : 0.0f, ms.w != 0.0f ? 1.0f : 0.0f };
            float tu[4] = { mt.x != 0.0f ? 1.0f : 0.0f, mt.y != 0.0f ? 1.0f : 0.0f,
                            mt.z != 0.0f ? 1.0f : 0.0f, mt.w != 0.0f ? 1.0f : 0.0f };
            unsigned pd[4] = {0, 0, 0, 0};
            unsigned pr[4] = {0, 0, 0, 0};
#pragma unroll
            for (int c = 0; c < 3; c++) {
                float4 t = tgt[c * HH4 + i];
                float4 r = ref[c * HH4 + i];
                float4 in = inp[c * HH4 + i];
                float to[4] = {dn(t.x), dn(t.y), dn(t.z), dn(t.w)};
                float ro[4] = {dn(r.x), dn(r.y), dn(r.z), dn(r.w)};
                float io[4] = {fminf(fmaxf(in.x, 0.0f), 1.0f), fminf(fmaxf(in.y, 0.0f), 1.0f),
                               fminf(fmaxf(in.z, 0.0f), 1.0f), fminf(fmaxf(in.w, 0.0f), 1.0f)};
                float4 otm, orm, oim;
                float* potm = (float*)&otm; float* porm = (float*)&orm; float* poim = (float*)&oim;
#pragma unroll
                for (int j = 0; j < 4; j++) {
                    float rm = ro[j] * mu[j];
                    float tm = to[j] * tu[j];
                    potm[j] = tm;
                    porm[j] = rm;
                    poim[j] = io[j] * mu[j];
                    pd[j] |= (unsigned)binof(rm * 255.0f) << (8 * c);
                    pr[j] |= (unsigned)binof(tm * 255.0f) << (8 * c);
                }
                out[c * HH4 + i]          = otm;
                out[P4 + c * HH4 + i]     = orm;
                out[2 * P4 + c * HH4 + i] = oim;
            }
            ((uint4*)g_binD)[i] = make_uint4(pd[0], pd[1], pd[2], pd[3]);
            ((uint4*)g_binR)[i] = make_uint4(pr[0], pr[1], pr[2], pr[3]);
        }
    }
    gsync(true);   // barrier 1: bins, planes, zeroed hist/flags visible

    // ============ Phase B: histograms + scattered-pixel flags ============
    for (int t = tid; t < 6 * NBINS; t += TPB) sh[t] = 0;
    __syncthreads();
    {
        int base = bid * TPB * HBATCH + tid;
        int pd[HBATCH];
        unsigned bd[HBATCH], br[HBATCH];
        bool ok[HBATCH];
#pragma unroll
        for (int j = 0; j < HBATCH; j++) {
            int k = base + j * TPB;
            ok[j] = (k < NIDX);
            int kk = ok[j] ? k : 0;
            pd[j] = i0[kk] * H + i1[kk];
            bd[j] = g_binD[pd[j]];
            br[j] = g_binR[i2[kk] * H + i3[kk]];
        }
#pragma unroll
        for (int j = 0; j < HBATCH; j++) {
            if (!ok[j]) continue;
            atomicOr(&g_flag[pd[j] >> 5], 1u << (pd[j] & 31));
            atomicAdd(&sh[bd[j] & 255u], 1);
            atomicAdd(&sh[NBINS + ((bd[j] >> 8) & 255u)], 1);
            atomicAdd(&sh[2 * NBINS + ((bd[j] >> 16) & 255u)], 1);
            atomicAdd(&sh[3 * NBINS + (br[j] & 255u)], 1);
            atomicAdd(&sh[4 * NBINS + ((br[j] >> 8) & 255u)], 1);
            atomicAdd(&sh[5 * NBINS + ((br[j] >> 16) & 255u)], 1);
        }
        __syncthreads();
        for (int t = tid; t < 6 * NBINS; t += TPB) {
            int v = sh[t];
            if (v) atomicAdd(&g_hist[t], v);
        }
    }
    gsync(true);   // barrier 2: full histogram + flags visible

    // ============ Phase C: table (per-block) + fused match build + loss ===
    {
        int b = tid;   // 256 threads
        // counts are integers <= 400000 < 2^24: parallel scan exact in f32
#pragma unroll
        for (int c = 0; c < 6; c++) cdf[c][b] = (float)g_hist[c * NBINS + b];
        __syncthreads();
        for (int off = 1; off < NBINS; off <<= 1) {
            float v[6];
#pragma unroll
            for (int c = 0; c < 6; c++) v[c] = (b >= off) ? cdf[c][b - off] : 0.0f;
            __syncthreads();
#pragma unroll
            for (int c = 0; c < 6; c++) cdf[c][b] += v[c];
            __syncthreads();
        }
#pragma unroll
        for (int c = 0; c < 6; c++) cdf[c][b] = __fdiv_rn(cdf[c][b], (float)NIDX);
        __syncthreads();
        // transfer table via lower_bound (equivalent to the linear first-match:
        // minimal m in [1,255] with cr[m] >= r; match iff cr[m-1] <= r)
#pragma unroll
        for (int c = 0; c < 3; c++) {
            int tab;
            if (b == NBINS - 1) {
                tab = NBINS - 1;
            } else {
                float r = cdf[c][b];
                const float* cr = cdf[3 + c];
                int lo = 1, hi = NBINS - 1;
                while (lo < hi) {
                    int mid = (lo + hi) >> 1;
                    if (cr[mid] >= r) hi = mid; else lo = mid + 1;
                }
                tab = (cr[lo - 1] <= r) ? lo : b;
            }
            stab[c][b] = __fdiv_rn((float)tab, 255.0f);
        }
        __syncthreads();

        // fused: match = flagged ? stab[bin] : rm ; loss += |im - match|
        const float4* rm4p = (const float4*)(outf + (size_t)P);
        const float4* im4p = (const float4*)(outf + (size_t)2 * P);
        float4*       mt4p = (float4*)(outf + (size_t)3 * P);
        float local = 0.0f;
        int base = bid * (TPB * EW_IT);
#pragma unroll
        for (int it = 0; it < EW_IT; it++) {
            int i = base + it * TPB + tid;           // pixel-group [0, HH4)
            uint4 bg = ((uint4*)g_binD)[i];
            unsigned fw = g_flag[i >> 3];
            unsigned bj[4] = {bg.x, bg.y, bg.z, bg.w};
            float4 rmv[3], imv[3];
#pragma unroll
            for (int c = 0; c < 3; c++) {
                rmv[c] = rm4p[c * HH4 + i];
                imv[c] = im4p[c * HH4 + i];
            }
            int bitbase = 4 * (i & 7);
#pragma unroll
            for (int c = 0; c < 3; c++) {
                float4 m4;
                float* pm = (float*)&m4;
                const float* prm = (const float*)&rmv[c];
                const float* pim = (const float*)&imv[c];
#pragma unroll
                for (int j = 0; j < 4; j++) {
                    bool fl = (fw >> (bitbase + j)) & 1u;
                    float m = fl ? stab[c][(bj[j] >> (8 * c)) & 255u] : prm[j];
                    pm[j] = m;
                    local += fabsf(pim[j] - m);
                }
                mt4p[c * HH4 + i] = m4;
            }
        }
        // block reduce
        __shared__ float ws[8];
#pragma unroll
        for (int off = 16; off; off >>= 1) local += __shfl_down_sync(0xFFFFFFFFu, local, off);
        if ((tid & 31) == 0) ws[tid >> 5] = local;
        __syncthreads();
        if (tid < 32) {
            float v = (tid < 8) ? ws[tid] : 0.0f;
#pragma unroll
            for (int off = 4; off; off >>= 1) v += __shfl_down_sync(0xFFFFFFFFu, v, off);
            if (tid == 0) g_pls[bid] = v;
        }
    }
    gsync(bid == 0);   // barrier 3: partials visible; only block 0 spins

    if (bid != 0) return;

    // ============ block 0: final reduction + write loss ==================
    {
        __shared__ double sred[TPB];
        double tot = 0.0;
        for (int i = tid; i < GRID; i += TPB) tot += (double)g_pls[i];
        sred[tid] = tot;
        __syncthreads();
        for (int s = TPB / 2; s; s >>= 1) {
            if (tid < s) sred[tid] += sred[tid + s];
            __syncthreads();
        }
        if (tid == 0) outf[(size_t)4 * P] = (float)(sred[0] / (double)P);
    }
}

// ---------------- launch -------------------------------------------------
extern "C" void kernel_launch(void* const* d_in, const int* in_sizes, int n_in,
                              void* d_out, int out_size) {
    const float* inp  = (const float*)d_in[0];
    const float* tgt  = (const float*)d_in[1];
    const float* ref  = (const float*)d_in[2];
    const float* msrc = (const float*)d_in[3];
    const float* mtar = (const float*)d_in[4];
    // d_in[5] = target_data_eye (unused by reference)
    const int* i0 = (const int*)d_in[6];
    const int* i1 = (const int*)d_in[7];
    const int* i2 = (const int*)d_in[8];
    const int* i3 = (const int*)d_in[9];

    mega_k<<<GRID, TPB>>>((const float4*)inp, (const float4*)tgt,
                          (const float4*)ref, (const float4*)msrc,
                          (const float4*)mtar, i0, i1, i2, i3,
                          (float4*)d_out);
}

// round 16
// speedup vs baseline: 2.0806x; 1.0933x over previous
#include <cuda_runtime.h>

#define H      1024
#define HH     (H * H)
#define P      (3 * HH)
#define P4     (P / 4)
#define HH4    (HH / 4)
#define NBINS  256
#define NIDX   400000
#define NFLAG  (HH / 32)              // 32768 bitmap words

#define GRID   592                    // exactly 4 blocks/SM * 148 SMs (RF-capacity fill)
#define TPB    256
#define STRIDE (GRID * TPB)           // 151552
#define HBATCH 3                      // 592*256*3 = 454656 >= NIDX

// ---------------- device scratch (no allocation allowed) ----------------
__device__ int                g_hist[6 * NBINS];
__device__ unsigned           g_binD[HH];   // packed bins of ref_masked (b0|b1<<8|b2<<16)
__device__ unsigned           g_binR[HH];   // packed bins of target_masked
__device__ unsigned           g_flag[NFLAG];// "pixel was scattered" bitmap
__device__ float              g_pls[GRID];  // per-block loss partials (slot-per-block)
__device__ unsigned long long g_tick;       // monotonic barrier ticket (never reset)

__device__ __forceinline__ float dn(float x) {
    float v = (x + 1.0f) * 0.5f;
    return fminf(fmaxf(v, 0.0f), 1.0f);
}
__device__ __forceinline__ int binof(float v255) { return min((int)v255, NBINS - 1); }

// Device-wide barrier: monotonic ticket, all blocks hit every barrier, so
// arrivals group into consecutive runs of GRID. Safe across graph replays.
__device__ __forceinline__ void gsync(bool spin) {
    __syncthreads();
    if (threadIdx.x == 0) {
        __threadfence();
        unsigned long long t = atomicAdd(&g_tick, 1ULL) + 1ULL;
        if (spin) {
            unsigned long long tgt = ((t + GRID - 1) / GRID) * (unsigned long long)GRID;
            unsigned long long cur;
            do {
                asm volatile("ld.global.acquire.gpu.u64 %0, [%1];"
                             : "=l"(cur) : "l"(&g_tick));
                if (cur >= tgt) break;
                __nanosleep(64);
            } while (true);
        }
    }
    __syncthreads();
}

__global__ void __launch_bounds__(TPB, 4)
mega_k(const float4* __restrict__ inp, const float4* __restrict__ tgt,
       const float4* __restrict__ ref, const float4* __restrict__ msrc,
       const float4* __restrict__ mtar,
       const int* __restrict__ i0, const int* __restrict__ i1,
       const int* __restrict__ i2, const int* __restrict__ i3,
       float4* __restrict__ out) {
    __shared__ int   sh[6 * NBINS];
    __shared__ float cdf[6][NBINS];
    __shared__ float stab[3][NBINS];
    const int tid = threadIdx.x;
    const int bid = blockIdx.x;
    float* outf = (float*)out;

    // ============ Phase A: elementwise transforms + bin packing ==========
    // (match plane NOT written here; built coalesced in phase C)
    if (bid == 0)
        for (int t = tid; t < 6 * NBINS; t += TPB) g_hist[t] = 0;
    {
        int gtid = bid * TPB + tid;
        if (gtid < NFLAG) g_flag[gtid] = 0u;
    }
    for (int i = bid * TPB + tid; i < HH4; i += STRIDE) {   // pixel-group [0, HH4)
        float4 ms = msrc[i];
        float4 mt = mtar[i];
        float mu[4] = { ms.x != 0.0f ? 1.0f : 0.0f, ms.y != 0.0f ? 1.0f : 0.0f,
                        ms.z != 0.0f ? 1.0f : 0.0f, ms.w != 0.0f ? 1.0f : 0.0f };
        float tu[4] = { mt.x != 0.0f ? 1.0f : 0.0f, mt.y != 0.0f ? 1.0f : 0.0f,
                        mt.z != 0.0f ? 1.0f : 0.0f, mt.w != 0.0f ? 1.0f : 0.0f };
        unsigned pd[4] = {0, 0, 0, 0};
        unsigned pr[4] = {0, 0, 0, 0};
#pragma unroll
        for (int c = 0; c < 3; c++) {
            float4 t = tgt[c * HH4 + i];
            float4 r = ref[c * HH4 + i];
            float4 in = inp[c * HH4 + i];
            float to[4] = {dn(t.x), dn(t.y), dn(t.z), dn(t.w)};
            float ro[4] = {dn(r.x), dn(r.y), dn(r.z), dn(r.w)};
            float io[4] = {fminf(fmaxf(in.x, 0.0f), 1.0f), fminf(fmaxf(in.y, 0.0f), 1.0f),
                           fminf(fmaxf(in.z, 0.0f), 1.0f), fminf(fmaxf(in.w, 0.0f), 1.0f)};
            float4 otm, orm, oim;
            float* potm = (float*)&otm; float* porm = (float*)&orm; float* poim = (float*)&oim;
#pragma unroll
            for (int j = 0; j < 4; j++) {
                float rm = ro[j] * mu[j];
                float tm = to[j] * tu[j];
                potm[j] = tm;
                porm[j] = rm;
                poim[j] = io[j] * mu[j];
                pd[j] |= (unsigned)binof(rm * 255.0f) << (8 * c);
                pr[j] |= (unsigned)binof(tm * 255.0f) << (8 * c);
            }
            out[c * HH4 + i]          = otm;
            out[P4 + c * HH4 + i]     = orm;
            out[2 * P4 + c * HH4 + i] = oim;
        }
        ((uint4*)g_binD)[i] = make_uint4(pd[0], pd[1], pd[2], pd[3]);
        ((uint4*)g_binR)[i] = make_uint4(pr[0], pr[1], pr[2], pr[3]);
    }
    gsync(true);   // barrier 1: bins, planes, zeroed hist/flags visible

    // ============ Phase B: histograms + scattered-pixel flags ============
    for (int t = tid; t < 6 * NBINS; t += TPB) sh[t] = 0;
    __syncthreads();
    {
        int base = bid * TPB + tid;
        int pd[HBATCH];
        unsigned bd[HBATCH], br[HBATCH];
        bool ok[HBATCH];
#pragma unroll
        for (int j = 0; j < HBATCH; j++) {
            int k = base + j * STRIDE;
            ok[j] = (k < NIDX);
            int kk = ok[j] ? k : 0;
            pd[j] = i0[kk] * H + i1[kk];
            bd[j] = g_binD[pd[j]];
            br[j] = g_binR[i2[kk] * H + i3[kk]];
        }
#pragma unroll
        for (int j = 0; j < HBATCH; j++) {
            if (!ok[j]) continue;
            atomicOr(&g_flag[pd[j] >> 5], 1u << (pd[j] & 31));
            atomicAdd(&sh[bd[j] & 255u], 1);
            atomicAdd(&sh[NBINS + ((bd[j] >> 8) & 255u)], 1);
            atomicAdd(&sh[2 * NBINS + ((bd[j] >> 16) & 255u)], 1);
            atomicAdd(&sh[3 * NBINS + (br[j] & 255u)], 1);
            atomicAdd(&sh[4 * NBINS + ((br[j] >> 8) & 255u)], 1);
            atomicAdd(&sh[5 * NBINS + ((br[j] >> 16) & 255u)], 1);
        }
        __syncthreads();
        for (int t = tid; t < 6 * NBINS; t += TPB) {
            int v = sh[t];
            if (v) atomicAdd(&g_hist[t], v);
        }
    }
    gsync(true);   // barrier 2: full histogram + flags visible

    // ============ Phase C: table (per-block) + fused match build + loss ===
    {
        int b = tid;   // 256 threads
        // counts are integers <= 400000 < 2^24: parallel scan exact in f32
#pragma unroll
        for (int c = 0; c < 6; c++) cdf[c][b] = (float)g_hist[c * NBINS + b];
        __syncthreads();
        for (int off = 1; off < NBINS; off <<= 1) {
            float v[6];
#pragma unroll
            for (int c = 0; c < 6; c++) v[c] = (b >= off) ? cdf[c][b - off] : 0.0f;
            __syncthreads();
#pragma unroll
            for (int c = 0; c < 6; c++) cdf[c][b] += v[c];
            __syncthreads();
        }
#pragma unroll
        for (int c = 0; c < 6; c++) cdf[c][b] = __fdiv_rn(cdf[c][b], (float)NIDX);
        __syncthreads();
        // transfer table via lower_bound (equivalent to the linear first-match:
        // minimal m in [1,255] with cr[m] >= r; match iff cr[m-1] <= r)
#pragma unroll
        for (int c = 0; c < 3; c++) {
            int tab;
            if (b == NBINS - 1) {
                tab = NBINS - 1;
            } else {
                float r = cdf[c][b];
                const float* cr = cdf[3 + c];
                int lo = 1, hi = NBINS - 1;
                while (lo < hi) {
                    int mid = (lo + hi) >> 1;
                    if (cr[mid] >= r) hi = mid; else lo = mid + 1;
                }
                tab = (cr[lo - 1] <= r) ? lo : b;
            }
            stab[c][b] = __fdiv_rn((float)tab, 255.0f);
        }
        __syncthreads();

        // fused: match = flagged ? stab[bin] : rm ; loss += |im - match|
        const float4* rm4p = (const float4*)(outf + (size_t)P);
        const float4* im4p = (const float4*)(outf + (size_t)2 * P);
        float4*       mt4p = (float4*)(outf + (size_t)3 * P);
        float local = 0.0f;
        for (int i = bid * TPB + tid; i < HH4; i += STRIDE) {   // pixel-group
            uint4 bg = ((uint4*)g_binD)[i];
            unsigned fw = g_flag[i >> 3];
            unsigned bj[4] = {bg.x, bg.y, bg.z, bg.w};
            float4 rmv[3], imv[3];
#pragma unroll
            for (int c = 0; c < 3; c++) {
                rmv[c] = rm4p[c * HH4 + i];
                imv[c] = im4p[c * HH4 + i];
            }
            int bitbase = 4 * (i & 7);
#pragma unroll
            for (int c = 0; c < 3; c++) {
                float4 m4;
                float* pm = (float*)&m4;
                const float* prm = (const float*)&rmv[c];
                const float* pim = (const float*)&imv[c];
#pragma unroll
                for (int j = 0; j < 4; j++) {
                    bool fl = (fw >> (bitbase + j)) & 1u;
                    float m = fl ? stab[c][(bj[j] >> (8 * c)) & 255u] : prm[j];
                    pm[j] = m;
                    local += fabsf(pim[j] - m);
                }
                mt4p[c * HH4 + i] = m4;
            }
        }
        // block reduce
        __shared__ float ws[8];
#pragma unroll
        for (int off = 16; off; off >>= 1) local += __shfl_down_sync(0xFFFFFFFFu, local, off);
        if ((tid & 31) == 0) ws[tid >> 5] = local;
        __syncthreads();
        if (tid < 32) {
            float v = (tid < 8) ? ws[tid] : 0.0f;
#pragma unroll
            for (int off = 4; off; off >>= 1) v += __shfl_down_sync(0xFFFFFFFFu, v, off);
            if (tid == 0) g_pls[bid] = v;
        }
    }
    gsync(bid == 0);   // barrier 3: partials visible; only block 0 spins

    if (bid != 0) return;

    // ============ block 0: final reduction + write loss ==================
    {
        __shared__ double sred[TPB];
        double tot = 0.0;
        for (int i = tid; i < GRID; i += TPB) tot += (double)g_pls[i];
        sred[tid] = tot;
        __syncthreads();
        for (int s = TPB / 2; s; s >>= 1) {
            if (tid < s) sred[tid] += sred[tid + s];
            __syncthreads();
        }
        if (tid == 0) outf[(size_t)4 * P] = (float)(sred[0] / (double)P);
    }
}

// ---------------- launch -------------------------------------------------
extern "C" void kernel_launch(void* const* d_in, const int* in_sizes, int n_in,
                              void* d_out, int out_size) {
    const float* inp  = (const float*)d_in[0];
    const float* tgt  = (const float*)d_in[1];
    const float* ref  = (const float*)d_in[2];
    const float* msrc = (const float*)d_in[3];
    const float* mtar = (const float*)d_in[4];
    // d_in[5] = target_data_eye (unused by reference)
    const int* i0 = (const int*)d_in[6];
    const int* i1 = (const int*)d_in[7];
    const int* i2 = (const int*)d_in[8];
    const int* i3 = (const int*)d_in[9];

    mega_k<<<GRID, TPB>>>((const float4*)inp, (const float4*)tgt,
                          (const float4*)ref, (const float4*)msrc,
                          (const float4*)mtar, i0, i1, i2, i3,
                          (float4*)d_out);
}